// round 1
// baseline (speedup 1.0000x reference)
#include <cuda_runtime.h>
#include <math.h>

// Problem constants
#define BB   32
#define HH   56
#define WWI  56
#define CC   384
#define NHH  12
#define WSS  7
#define SSS  3
#define NT   49          // tokens per window
#define NWW  64          // windows per image
#define HDD  32          // head dim
#define MLPH 1536
#define MTOK (BB * HH * WWI)   // 100352 rows

// ---------------- scratch (static device globals; no allocations) ------------
__device__ float g_xw [(size_t)MTOK * CC];     // LN1+shift+partition output / attn output (reused)
__device__ float g_big[(size_t)MTOK * MLPH];   // qkv output (1152 cols) / fc1+gelu output (1536 cols)
__device__ float g_y  [(size_t)MTOK * CC];     // post-attention residual x
__device__ float g_h  [(size_t)MTOK * CC];     // LN2 output

// Map a window-token row index m -> image row index (used both for the
// shift+partition gather (LN1) and the reverse+unshift scatter (proj)).
__device__ __forceinline__ int swin_map(int m) {
    int bb  = m / (NWW * NT);
    int rem = m - bb * (NWW * NT);
    int win = rem / NT;
    int t   = rem - win * NT;
    int wy = win >> 3, wx = win & 7;
    int ty = t / 7,    tx = t - (t / 7) * 7;
    int h0 = wy * 7 + ty + SSS; if (h0 >= HH)  h0 -= HH;
    int w0 = wx * 7 + tx + SSS; if (w0 >= WWI) w0 -= WWI;
    return bb * (HH * WWI) + h0 * WWI + w0;
}

// ---------------- LayerNorm kernels (1 warp per token) -----------------------
// MODE 0: g_xw[m] = LN(in[swin_map(m)])  (LN1 + shift + window partition)
// MODE 1: g_h[m]  = LN(g_y[m])           (LN2)
template <int MODE>
__global__ __launch_bounds__(256) void ln_kernel(const float* __restrict__ in,
                                                 const float* __restrict__ w,
                                                 const float* __restrict__ b) {
    int warp = (blockIdx.x * 256 + threadIdx.x) >> 5;
    int lane = threadIdx.x & 31;
    const float* src;
    float* dst;
    if (MODE == 0) {
        src = in + (size_t)swin_map(warp) * CC;
        dst = g_xw + (size_t)warp * CC;
    } else {
        src = g_y + (size_t)warp * CC;
        dst = g_h + (size_t)warp * CC;
    }
    float v[12];
    float s = 0.f, sq = 0.f;
#pragma unroll
    for (int i = 0; i < 12; i++) {
        float t = src[lane + i * 32];
        v[i] = t; s += t; sq += t * t;
    }
#pragma unroll
    for (int o = 16; o; o >>= 1) {
        s  += __shfl_xor_sync(0xFFFFFFFFu, s,  o);
        sq += __shfl_xor_sync(0xFFFFFFFFu, sq, o);
    }
    float mean = s * (1.f / CC);
    float rstd = rsqrtf(sq * (1.f / CC) - mean * mean + 1e-5f);
#pragma unroll
    for (int i = 0; i < 12; i++) {
        int c = lane + i * 32;
        dst[c] = (v[i] - mean) * rstd * w[c] + b[c];
    }
}

// ---------------- tiled fp32 GEMM: C = A(MxK) * B(KxN) + bias, epilogues -----
// EPI 0: qkv   A=g_xw,  C=g_big                 (N=1152, K=384)
// EPI 1: fc1   A=g_h,   C=g_big, GELU           (N=1536, K=384)
// EPI 2: proj  A=g_xw,  C=g_y, scatter + res(x) (N=384,  K=384)   aux = x input
// EPI 3: fc2   A=g_big, C=out, + res(g_y)       (N=384,  K=1536)  Cp = d_out
#define TM 128
#define TN 64
#define TK 16

template <int EPI>
__global__ __launch_bounds__(256) void gemm_kernel(const float* __restrict__ Bw,
                                                   const float* __restrict__ bias,
                                                   const float* __restrict__ aux,
                                                   float* __restrict__ Cp,
                                                   int N, int K) {
    __shared__ __align__(16) float As[TM][TK + 4];
    __shared__ __align__(16) float Bs[TK][TN];

    const float* A = (EPI == 0 || EPI == 2) ? g_xw : (EPI == 1 ? g_h : g_big);
    float* C = (EPI == 0 || EPI == 1) ? g_big : (EPI == 2 ? g_y : Cp);

    int tid = threadIdx.x;
    int m0 = blockIdx.y * TM;
    int n0 = blockIdx.x * TN;
    int tx = tid & 15;          // 16 cols of threads -> 4 output cols each
    int ty = tid >> 4;          // 16 rows of threads -> 8 output rows each

    float acc[8][4] = {};

    int ar = tid >> 1;                 // 0..127
    int ak = (tid & 1) << 3;           // 0 or 8
    int br = tid >> 4;                 // 0..15
    int bc = (tid & 15) << 2;          // 0..60

    for (int k0 = 0; k0 < K; k0 += TK) {
        const float* Ap = A + (size_t)(m0 + ar) * K + k0 + ak;
        float4 a0 = *(const float4*)Ap;
        float4 a1 = *(const float4*)(Ap + 4);
        *(float4*)&As[ar][ak]     = a0;
        *(float4*)&As[ar][ak + 4] = a1;
        *(float4*)&Bs[br][bc] = *(const float4*)&Bw[(size_t)(k0 + br) * N + n0 + bc];
        __syncthreads();
#pragma unroll
        for (int kk = 0; kk < TK; kk++) {
            float bv[4];
            *(float4*)bv = *(const float4*)&Bs[kk][tx << 2];
            float av[8];
#pragma unroll
            for (int r = 0; r < 8; r++) av[r] = As[ty * 8 + r][kk];
#pragma unroll
            for (int r = 0; r < 8; r++)
#pragma unroll
                for (int c = 0; c < 4; c++) acc[r][c] += av[r] * bv[c];
        }
        __syncthreads();
    }

    int row_base = m0 + ty * 8;
    int col_base = n0 + (tx << 2);
#pragma unroll
    for (int r = 0; r < 8; r++) {
        int row = row_base + r;
        int dst = (EPI == 2) ? swin_map(row) : row;
#pragma unroll
        for (int c = 0; c < 4; c++) {
            int col = col_base + c;
            float vv = acc[r][c] + bias[col];
            if (EPI == 1) vv = 0.5f * vv * (1.f + erff(vv * 0.70710678118654752f));
            if (EPI == 2) vv += aux[(size_t)dst * CC + col];              // + shortcut x
            if (EPI == 3) vv += g_y[(size_t)row * CC + col];              // + attn residual
            if (EPI == 2) C[(size_t)dst * CC + col] = vv;
            else          C[(size_t)row * N  + col] = vv;
        }
    }
}

// ---------------- fused window attention (one block per (window, head)) ------
// reads g_big (qkv, row stride 1152), writes g_xw (row stride 384)
__global__ __launch_bounds__(256) void attn_kernel(const float* __restrict__ rpb) {
    __shared__ float q[56 * 33];
    __shared__ float k[56 * 33];
    __shared__ float v[56 * 33];
    __shared__ float S[56 * 57];

    int blk = blockIdx.x;
    int win = blk / NHH;
    int hd  = blk - win * NHH;
    const float* base = g_big + (size_t)win * NT * (3 * CC) + hd * HDD;
    int tid = threadIdx.x;

    for (int p = tid; p < 56 * 32; p += 256) {
        int i = p >> 5, d = p & 31;
        float qq = 0.f, kk = 0.f, vv = 0.f;
        if (i < NT) {
            size_t off = (size_t)i * (3 * CC) + d;
            qq = base[off];
            kk = base[off + CC];
            vv = base[off + 2 * CC];
        }
        q[i * 33 + d] = qq;
        k[i * 33 + d] = kk;
        v[i * 33 + d] = vv;
    }
    __syncthreads();

    int wloc = win & 63;
    int wy = wloc >> 3, wx = wloc & 7;
    const float scale = 0.17677669529663689f;   // 1/sqrt(32)

    // S = q k^T * scale + rel-pos bias + shift mask   (padded to 56x56)
    if (tid < 196) {
        int ti = (tid / 14) * 4;
        int tj = (tid % 14) * 4;
        float acc[4][4] = {};
#pragma unroll
        for (int d = 0; d < 32; d++) {
            float a[4], bq[4];
#pragma unroll
            for (int r = 0; r < 4; r++) a[r]  = q[(ti + r) * 33 + d];
#pragma unroll
            for (int c = 0; c < 4; c++) bq[c] = k[(tj + c) * 33 + d];
#pragma unroll
            for (int r = 0; r < 4; r++)
#pragma unroll
                for (int c = 0; c < 4; c++) acc[r][c] += a[r] * bq[c];
        }
#pragma unroll
        for (int r = 0; r < 4; r++) {
#pragma unroll
            for (int c = 0; c < 4; c++) {
                int i = ti + r, j = tj + c;
                float bias = 0.f, msk = 0.f;
                if (i < NT && j < NT) {
                    int iy = i / 7, ix = i - iy * 7;
                    int jy = j / 7, jx = j - jy * 7;
                    bias = rpb[((iy - jy + 6) * 13 + (ix - jx + 6)) * NHH + hd];
                    int his = wy * 7 + iy, wis = wx * 7 + ix;
                    int hjs = wy * 7 + jy, wjs = wx * 7 + jx;
                    int ri = (his < 49 ? 0 : (his < 53 ? 1 : 2)) * 3 + (wis < 49 ? 0 : (wis < 53 ? 1 : 2));
                    int rj = (hjs < 49 ? 0 : (hjs < 53 ? 1 : 2)) * 3 + (wjs < 49 ? 0 : (wjs < 53 ? 1 : 2));
                    msk = (ri == rj) ? 0.f : -100.f;
                }
                S[i * 57 + j] = acc[r][c] * scale + bias + msk;
            }
        }
    }
    __syncthreads();

    // row softmax (only the 49 real rows / 49 real cols)
    if (tid < NT) {
        float* row = S + tid * 57;
        float mx = row[0];
        for (int j = 1; j < NT; j++) mx = fmaxf(mx, row[j]);
        float sum = 0.f;
        for (int j = 0; j < NT; j++) { float e = __expf(row[j] - mx); row[j] = e; sum += e; }
        float inv = 1.f / sum;
        for (int j = 0; j < NT; j++) row[j] *= inv;
    }
    __syncthreads();

    // out = P @ v  (rows padded to 56)
    if (tid < 112) {
        int ti = (tid >> 3) * 4;   // 14 row groups
        int tc = (tid & 7) * 4;    // 8 col groups
        float acc[4][4] = {};
        for (int j = 0; j < NT; j++) {
            float a[4], bv[4];
#pragma unroll
            for (int r = 0; r < 4; r++) a[r]  = S[(ti + r) * 57 + j];
#pragma unroll
            for (int c = 0; c < 4; c++) bv[c] = v[j * 33 + tc + c];
#pragma unroll
            for (int r = 0; r < 4; r++)
#pragma unroll
                for (int c = 0; c < 4; c++) acc[r][c] += a[r] * bv[c];
        }
        float* out = g_xw + (size_t)win * NT * CC + hd * HDD;
#pragma unroll
        for (int r = 0; r < 4; r++) {
            int i = ti + r;
            if (i < NT) {
#pragma unroll
                for (int c = 0; c < 4; c++)
                    out[(size_t)i * CC + tc + c] = acc[r][c];
            }
        }
    }
}

// -----------------------------------------------------------------------------
extern "C" void kernel_launch(void* const* d_in, const int* in_sizes, int n_in,
                              void* d_out, int out_size) {
    const float* x     = (const float*)d_in[0];
    const float* n1w   = (const float*)d_in[1];
    const float* n1b   = (const float*)d_in[2];
    const float* qkvw  = (const float*)d_in[3];
    const float* qkvb  = (const float*)d_in[4];
    const float* rpb   = (const float*)d_in[5];
    const float* projw = (const float*)d_in[6];
    const float* projb = (const float*)d_in[7];
    const float* n2w   = (const float*)d_in[8];
    const float* n2b   = (const float*)d_in[9];
    const float* fc1w  = (const float*)d_in[10];
    const float* fc1b  = (const float*)d_in[11];
    const float* fc2w  = (const float*)d_in[12];
    const float* fc2b  = (const float*)d_in[13];
    float* out = (float*)d_out;

    // 1) LN1 + cyclic shift + window partition -> g_xw
    ln_kernel<0><<<MTOK / 8, 256>>>(x, n1w, n1b);
    // 2) QKV GEMM -> g_big (100352 x 1152)
    gemm_kernel<0><<<dim3(1152 / TN, MTOK / TM), 256>>>(qkvw, qkvb, nullptr, nullptr, 1152, CC);
    // 3) windowed attention (bias + shift mask + softmax) -> g_xw
    attn_kernel<<<BB * NWW * NHH, 256>>>(rpb);
    // 4) proj GEMM + window reverse + unshift + residual(x) -> g_y
    gemm_kernel<2><<<dim3(CC / TN, MTOK / TM), 256>>>(projw, projb, x, nullptr, CC, CC);
    // 5) LN2 -> g_h
    ln_kernel<1><<<MTOK / 8, 256>>>(nullptr, n2w, n2b);
    // 6) FC1 GEMM + exact GELU -> g_big (100352 x 1536)
    gemm_kernel<1><<<dim3(MLPH / TN, MTOK / TM), 256>>>(fc1w, fc1b, nullptr, nullptr, MLPH, CC);
    // 7) FC2 GEMM + residual(g_y) -> d_out
    gemm_kernel<3><<<dim3(CC / TN, MTOK / TM), 256>>>(fc2w, fc2b, nullptr, out, CC, MLPH);
}

// round 4
// speedup vs baseline: 2.1191x; 2.1191x over previous
#include <cuda_runtime.h>
#include <cuda_bf16.h>
#include <math.h>
#include <stdint.h>

// Problem constants
#define BB   32
#define HH   56
#define WWI  56
#define CC   384
#define NHH  12
#define SSS  3
#define NT   49
#define NWW  64
#define HDD  32
#define MLPH 1536
#define MTOK (BB * HH * WWI)   // 100352 rows

// ---------------- scratch (static device globals; no allocations) ------------
__device__ float g_xw [(size_t)MTOK * CC];     // LN1 out / attn out
__device__ float g_big[(size_t)MTOK * MLPH];   // qkv (1152) / fc1+gelu (1536)
__device__ float g_y  [(size_t)MTOK * CC];     // post-attention residual
__device__ float g_h  [(size_t)MTOK * CC];     // LN2 out

// ---------------- helpers ----------------------------------------------------
__device__ __forceinline__ uint32_t smem_u32(const void* p) {
    uint32_t a;
    asm("{ .reg .u64 t; cvta.to.shared.u64 t, %1; cvt.u32.u64 %0, t; }" : "=r"(a) : "l"(p));
    return a;
}

#define LDSM4(R0, R1, R2, R3, ADDR) \
    asm volatile("ldmatrix.sync.aligned.m8n8.x4.shared.b16 {%0,%1,%2,%3}, [%4];" \
                 : "=r"(R0), "=r"(R1), "=r"(R2), "=r"(R3) : "r"(ADDR))

#define MMA16816(D, A, B) \
    asm volatile("mma.sync.aligned.m16n8k16.row.col.f32.bf16.bf16.f32 " \
                 "{%0,%1,%2,%3}, {%4,%5,%6,%7}, {%8,%9}, {%0,%1,%2,%3};" \
                 : "+f"((D)[0]), "+f"((D)[1]), "+f"((D)[2]), "+f"((D)[3]) \
                 : "r"((A)[0]), "r"((A)[1]), "r"((A)[2]), "r"((A)[3]), \
                   "r"((B)[0]), "r"((B)[1]))

__device__ __forceinline__ int swin_map(int m) {
    int bb  = m / (NWW * NT);
    int rem = m - bb * (NWW * NT);
    int win = rem / NT;
    int t   = rem - win * NT;
    int wy = win >> 3, wx = win & 7;
    int ty = t / 7,    tx = t - (t / 7) * 7;
    int h0 = wy * 7 + ty + SSS; if (h0 >= HH)  h0 -= HH;
    int w0 = wx * 7 + tx + SSS; if (w0 >= WWI) w0 -= WWI;
    return bb * (HH * WWI) + h0 * WWI + w0;
}

// fp32 -> (hi bf16, lo bf16) split store of a float4 (4 hi bytes8, 4 lo bytes8)
__device__ __forceinline__ void cvt_store(char* hp, char* lp, float4 v) {
    __nv_bfloat162 h01 = __floats2bfloat162_rn(v.x, v.y);
    __nv_bfloat162 h23 = __floats2bfloat162_rn(v.z, v.w);
    float lx = v.x - __bfloat162float(__low2bfloat16(h01));
    float ly = v.y - __bfloat162float(__high2bfloat16(h01));
    float lz = v.z - __bfloat162float(__low2bfloat16(h23));
    float lw = v.w - __bfloat162float(__high2bfloat16(h23));
    __nv_bfloat162 l01 = __floats2bfloat162_rn(lx, ly);
    __nv_bfloat162 l23 = __floats2bfloat162_rn(lz, lw);
    *(uint2*)hp = make_uint2(*(uint32_t*)&h01, *(uint32_t*)&h23);
    *(uint2*)lp = make_uint2(*(uint32_t*)&l01, *(uint32_t*)&l23);
}

// ---------------- LayerNorm kernels (1 warp per token) -----------------------
template <int MODE>
__global__ __launch_bounds__(256) void ln_kernel(const float* __restrict__ in,
                                                 const float* __restrict__ w,
                                                 const float* __restrict__ b) {
    int warp = (blockIdx.x * 256 + threadIdx.x) >> 5;
    int lane = threadIdx.x & 31;
    const float* src;
    float* dst;
    if (MODE == 0) { src = in + (size_t)swin_map(warp) * CC;  dst = g_xw + (size_t)warp * CC; }
    else           { src = g_y + (size_t)warp * CC;           dst = g_h  + (size_t)warp * CC; }
    float v[12];
    float s = 0.f, sq = 0.f;
#pragma unroll
    for (int i = 0; i < 12; i++) {
        float t = src[lane + i * 32];
        v[i] = t; s += t; sq += t * t;
    }
#pragma unroll
    for (int o = 16; o; o >>= 1) {
        s  += __shfl_xor_sync(0xFFFFFFFFu, s,  o);
        sq += __shfl_xor_sync(0xFFFFFFFFu, sq, o);
    }
    float mean = s * (1.f / CC);
    float rstd = rsqrtf(sq * (1.f / CC) - mean * mean + 1e-5f);
#pragma unroll
    for (int i = 0; i < 12; i++) {
        int c = lane + i * 32;
        dst[c] = (v[i] - mean) * rstd * w[c] + b[c];
    }
}

// ---------------- mma.sync bf16-split GEMM: C = A(MxK)*B(KxN) + epi ----------
// EPI 0: qkv   A=g_xw,  C=g_big(1152)
// EPI 1: fc1   A=g_h,   C=g_big(1536), GELU
// EPI 2: proj  A=g_xw,  C=g_y, scatter+res(aux=x)
// EPI 3: fc2   A=g_big, C=Cp(out), +res(g_y)
#define SA       40              // smem row stride in bf16 elements (conflict-free)
#define A_TILE_B (128 * SA * 2)  // 10240 bytes per (hi or lo) tile
#define OFF_AHI  0
#define OFF_ALO  (A_TILE_B)
#define OFF_BHI  (2 * A_TILE_B)
#define OFF_BLO  (3 * A_TILE_B)
#define STAGE    (4 * A_TILE_B)  // 40960
#define SMEM_TOT (2 * STAGE)     // 81920

template <int EPI>
__global__ __launch_bounds__(256, 1) void gemm_mma(const float* __restrict__ Bw,
                                                   const float* __restrict__ bias,
                                                   const float* __restrict__ aux,
                                                   float* __restrict__ Cp,
                                                   int N, int K) {
    extern __shared__ __align__(128) char smem[];
    const uint32_t sb = smem_u32(smem);
    const int tid = threadIdx.x;
    const int lane = tid & 31;
    const int wid = tid >> 5;
    const int wr = wid >> 2;           // 0..1 : 64-row slab
    const int wc = wid & 3;            // 0..3 : 32-col slab
    const int m0 = blockIdx.y * 128;
    const int n0 = blockIdx.x * 128;

    const float* A = (EPI == 0 || EPI == 2) ? g_xw : (EPI == 1 ? g_h : g_big);

    float acc[4][4][4];
#pragma unroll
    for (int i = 0; i < 4; i++)
#pragma unroll
        for (int j = 0; j < 4; j++)
#pragma unroll
            for (int q = 0; q < 4; q++) acc[i][j][q] = 0.f;

    // prefetch registers
    float4 fa[4];
    float  fb[16];
    const int ar  = tid >> 1;            // A row 0..127
    const int ah  = (tid & 1) << 4;      // A col offset 0/16
    const int bn  = tid & 127;           // B n index
    const int bkh = (tid >> 7) << 4;     // B k offset 0/16

    const int NC = K >> 5;

    // prologue loads (chunk 0)
    {
        const float* p = A + (size_t)(m0 + ar) * K + ah;
#pragma unroll
        for (int q = 0; q < 4; q++) fa[q] = *(const float4*)(p + q * 4);
#pragma unroll
        for (int q = 0; q < 16; q++) fb[q] = Bw[(size_t)(bkh + q) * N + n0 + bn];
    }

    for (int c = 0; c < NC; c++) {
        const int st = c & 1;
        char* base = smem + st * STAGE;
        // ---- store prefetched chunk into smem (hi/lo bf16) ----
#pragma unroll
        for (int q = 0; q < 4; q++) {
            int off = (ar * SA + ah + q * 4) * 2;
            cvt_store(base + OFF_AHI + off, base + OFF_ALO + off, fa[q]);
        }
#pragma unroll
        for (int q = 0; q < 16; q++) {
            float w0 = fb[q];
            __nv_bfloat16 hb = __float2bfloat16(w0);
            __nv_bfloat16 lb = __float2bfloat16(w0 - __bfloat162float(hb));
            char* pb = base + OFF_BHI + (bn * SA + bkh + q) * 2;
            *(__nv_bfloat16*)pb = hb;
            *(__nv_bfloat16*)(pb + A_TILE_B) = lb;
        }
        __syncthreads();
        // ---- prefetch next chunk ----
        if (c + 1 < NC) {
            int k0 = (c + 1) << 5;
            const float* p = A + (size_t)(m0 + ar) * K + k0 + ah;
#pragma unroll
            for (int q = 0; q < 4; q++) fa[q] = *(const float4*)(p + q * 4);
#pragma unroll
            for (int q = 0; q < 16; q++) fb[q] = Bw[(size_t)(k0 + bkh + q) * N + n0 + bn];
        }
        // ---- MMA over this chunk (2 k16 steps) ----
        const uint32_t sbase = sb + st * STAGE;
        const int arow  = lane & 15;
        const int acol8 = (lane >> 4) << 3;
        const int brow  = ((lane >> 4) << 3) + (lane & 7);
        const int bcol8 = ((lane >> 3) & 1) << 3;
#pragma unroll
        for (int ks = 0; ks < 2; ks++) {
            uint32_t aH[4][4], aL[4][4], bH[4][2], bL[4][2];
#pragma unroll
            for (int mt = 0; mt < 4; mt++) {
                uint32_t ad = sbase + OFF_AHI +
                    ((wr * 64 + mt * 16 + arow) * SA + ks * 16 + acol8) * 2;
                LDSM4(aH[mt][0], aH[mt][1], aH[mt][2], aH[mt][3], ad);
                LDSM4(aL[mt][0], aL[mt][1], aL[mt][2], aL[mt][3], ad + A_TILE_B);
            }
#pragma unroll
            for (int nt2 = 0; nt2 < 2; nt2++) {
                uint32_t bd = sbase + OFF_BHI +
                    ((wc * 32 + nt2 * 16 + brow) * SA + ks * 16 + bcol8) * 2;
                uint32_t r0, r1, r2, r3;
                LDSM4(r0, r1, r2, r3, bd);
                bH[nt2 * 2][0] = r0; bH[nt2 * 2][1] = r1;
                bH[nt2 * 2 + 1][0] = r2; bH[nt2 * 2 + 1][1] = r3;
                LDSM4(r0, r1, r2, r3, bd + A_TILE_B);
                bL[nt2 * 2][0] = r0; bL[nt2 * 2][1] = r1;
                bL[nt2 * 2 + 1][0] = r2; bL[nt2 * 2 + 1][1] = r3;
            }
#pragma unroll
            for (int mt = 0; mt < 4; mt++) {
#pragma unroll
                for (int nt = 0; nt < 4; nt++) {
                    MMA16816(acc[mt][nt], aH[mt], bH[nt]);
                    MMA16816(acc[mt][nt], aH[mt], bL[nt]);
                    MMA16816(acc[mt][nt], aL[mt], bH[nt]);
                }
            }
        }
    }

    // ---- epilogue (fragment layout: c0,c1 @ (r, c..c+1), c2,c3 @ (r+8, .)) ----
    float* C = (EPI == 0 || EPI == 1) ? g_big : (EPI == 2 ? g_y : Cp);
#pragma unroll
    for (int mt = 0; mt < 4; mt++) {
#pragma unroll
        for (int nt = 0; nt < 4; nt++) {
            int col = n0 + wc * 32 + nt * 8 + (lane & 3) * 2;
            float bx = bias[col], by = bias[col + 1];
#pragma unroll
            for (int half = 0; half < 2; half++) {
                int row = m0 + wr * 64 + mt * 16 + (lane >> 2) + half * 8;
                float vx = acc[mt][nt][half * 2 + 0] + bx;
                float vy = acc[mt][nt][half * 2 + 1] + by;
                if (EPI == 1) {
                    vx = 0.5f * vx * (1.f + erff(vx * 0.70710678118654752f));
                    vy = 0.5f * vy * (1.f + erff(vy * 0.70710678118654752f));
                }
                if (EPI == 2) {
                    int dst = swin_map(row);
                    float2 a = *(const float2*)(aux + (size_t)dst * CC + col);
                    vx += a.x; vy += a.y;
                    *(float2*)(C + (size_t)dst * CC + col) = make_float2(vx, vy);
                } else if (EPI == 3) {
                    float2 a = *(const float2*)(g_y + (size_t)row * CC + col);
                    vx += a.x; vy += a.y;
                    *(float2*)(C + (size_t)row * CC + col) = make_float2(vx, vy);
                } else {
                    *(float2*)(C + (size_t)row * N + col) = make_float2(vx, vy);
                }
            }
        }
    }
}

// ---------------- fused window attention (one block per (window, head)) ------
__global__ __launch_bounds__(256) void attn_kernel(const float* __restrict__ rpb) {
    __shared__ float q[56 * 33];
    __shared__ float k[56 * 33];
    __shared__ float v[56 * 33];
    __shared__ float S[56 * 57];

    int blk = blockIdx.x;
    int win = blk / NHH;
    int hd  = blk - win * NHH;
    const float* base = g_big + (size_t)win * NT * (3 * CC) + hd * HDD;
    int tid = threadIdx.x;

    for (int p = tid; p < 56 * 32; p += 256) {
        int i = p >> 5, d = p & 31;
        float qq = 0.f, kk = 0.f, vv = 0.f;
        if (i < NT) {
            size_t off = (size_t)i * (3 * CC) + d;
            qq = base[off];
            kk = base[off + CC];
            vv = base[off + 2 * CC];
        }
        q[i * 33 + d] = qq;
        k[i * 33 + d] = kk;
        v[i * 33 + d] = vv;
    }
    __syncthreads();

    int wloc = win & 63;
    int wy = wloc >> 3, wx = wloc & 7;
    const float scale = 0.17677669529663689f;

    if (tid < 196) {
        int ti = (tid / 14) * 4;
        int tj = (tid % 14) * 4;
        float acc[4][4] = {};
#pragma unroll
        for (int d = 0; d < 32; d++) {
            float a[4], bq[4];
#pragma unroll
            for (int r = 0; r < 4; r++) a[r]  = q[(ti + r) * 33 + d];
#pragma unroll
            for (int c = 0; c < 4; c++) bq[c] = k[(tj + c) * 33 + d];
#pragma unroll
            for (int r = 0; r < 4; r++)
#pragma unroll
                for (int c = 0; c < 4; c++) acc[r][c] += a[r] * bq[c];
        }
#pragma unroll
        for (int r = 0; r < 4; r++) {
#pragma unroll
            for (int c = 0; c < 4; c++) {
                int i = ti + r, j = tj + c;
                float bias = 0.f, msk = 0.f;
                if (i < NT && j < NT) {
                    int iy = i / 7, ix = i - iy * 7;
                    int jy = j / 7, jx = j - jy * 7;
                    bias = rpb[((iy - jy + 6) * 13 + (ix - jx + 6)) * NHH + hd];
                    int his = wy * 7 + iy, wis = wx * 7 + ix;
                    int hjs = wy * 7 + jy, wjs = wx * 7 + jx;
                    int ri = (his < 49 ? 0 : (his < 53 ? 1 : 2)) * 3 + (wis < 49 ? 0 : (wis < 53 ? 1 : 2));
                    int rj = (hjs < 49 ? 0 : (hjs < 53 ? 1 : 2)) * 3 + (wjs < 49 ? 0 : (wjs < 53 ? 1 : 2));
                    msk = (ri == rj) ? 0.f : -100.f;
                }
                S[i * 57 + j] = acc[r][c] * scale + bias + msk;
            }
        }
    }
    __syncthreads();

    if (tid < NT) {
        float* row = S + tid * 57;
        float mx = row[0];
        for (int j = 1; j < NT; j++) mx = fmaxf(mx, row[j]);
        float sum = 0.f;
        for (int j = 0; j < NT; j++) { float e = __expf(row[j] - mx); row[j] = e; sum += e; }
        float inv = 1.f / sum;
        for (int j = 0; j < NT; j++) row[j] *= inv;
    }
    __syncthreads();

    if (tid < 112) {
        int ti = (tid >> 3) * 4;
        int tc = (tid & 7) * 4;
        float acc[4][4] = {};
        for (int j = 0; j < NT; j++) {
            float a[4], bv[4];
#pragma unroll
            for (int r = 0; r < 4; r++) a[r]  = S[(ti + r) * 57 + j];
#pragma unroll
            for (int c = 0; c < 4; c++) bv[c] = v[j * 33 + tc + c];
#pragma unroll
            for (int r = 0; r < 4; r++)
#pragma unroll
                for (int c = 0; c < 4; c++) acc[r][c] += a[r] * bv[c];
        }
        float* out = g_xw + (size_t)win * NT * CC + hd * HDD;
#pragma unroll
        for (int r = 0; r < 4; r++) {
            int i = ti + r;
            if (i < NT) {
#pragma unroll
                for (int c = 0; c < 4; c++)
                    out[(size_t)i * CC + tc + c] = acc[r][c];
            }
        }
    }
}

// -----------------------------------------------------------------------------
extern "C" void kernel_launch(void* const* d_in, const int* in_sizes, int n_in,
                              void* d_out, int out_size) {
    const float* x     = (const float*)d_in[0];
    const float* n1w   = (const float*)d_in[1];
    const float* n1b   = (const float*)d_in[2];
    const float* qkvw  = (const float*)d_in[3];
    const float* qkvb  = (const float*)d_in[4];
    const float* rpb   = (const float*)d_in[5];
    const float* projw = (const float*)d_in[6];
    const float* projb = (const float*)d_in[7];
    const float* n2w   = (const float*)d_in[8];
    const float* n2b   = (const float*)d_in[9];
    const float* fc1w  = (const float*)d_in[10];
    const float* fc1b  = (const float*)d_in[11];
    const float* fc2w  = (const float*)d_in[12];
    const float* fc2b  = (const float*)d_in[13];
    float* out = (float*)d_out;

    static bool attr_set = false;
    if (!attr_set) {
        cudaFuncSetAttribute(gemm_mma<0>, cudaFuncAttributeMaxDynamicSharedMemorySize, SMEM_TOT);
        cudaFuncSetAttribute(gemm_mma<1>, cudaFuncAttributeMaxDynamicSharedMemorySize, SMEM_TOT);
        cudaFuncSetAttribute(gemm_mma<2>, cudaFuncAttributeMaxDynamicSharedMemorySize, SMEM_TOT);
        cudaFuncSetAttribute(gemm_mma<3>, cudaFuncAttributeMaxDynamicSharedMemorySize, SMEM_TOT);
        attr_set = true;
    }

    // 1) LN1 + shift + window partition -> g_xw
    ln_kernel<0><<<MTOK / 8, 256>>>(x, n1w, n1b);
    // 2) QKV GEMM -> g_big (100352 x 1152)
    gemm_mma<0><<<dim3(1152 / 128, MTOK / 128), 256, SMEM_TOT>>>(qkvw, qkvb, nullptr, nullptr, 1152, CC);
    // 3) windowed attention -> g_xw
    attn_kernel<<<BB * NWW * NHH, 256>>>(rpb);
    // 4) proj GEMM + reverse/unshift scatter + residual(x) -> g_y
    gemm_mma<2><<<dim3(CC / 128, MTOK / 128), 256, SMEM_TOT>>>(projw, projb, x, nullptr, CC, CC);
    // 5) LN2 -> g_h
    ln_kernel<1><<<MTOK / 8, 256>>>(nullptr, n2w, n2b);
    // 6) FC1 GEMM + GELU -> g_big (100352 x 1536)
    gemm_mma<1><<<dim3(MLPH / 128, MTOK / 128), 256, SMEM_TOT>>>(fc1w, fc1b, nullptr, nullptr, MLPH, CC);
    // 7) FC2 GEMM + residual(g_y) -> d_out
    gemm_mma<3><<<dim3(CC / 128, MTOK / 128), 256, SMEM_TOT>>>(fc2w, fc2b, nullptr, out, CC, MLPH);
}